// round 2
// baseline (speedup 1.0000x reference)
#include <cuda_runtime.h>
#include <cstdint>

#define NB 4
#define NX 64
#define NY 64
#define NZ 40
#define C  32
#define KM 16    // complex-axis kept modes (x for xz/xy, y for yz)
#define KZM 16   // z real-axis kept modes  {0..7} u {13..20}
#define KYM 32   // y real-axis kept modes  {0..15} u {17..32}

// ---------------- twiddle tables ----------------
__device__ float2 g_Ex [KM*NX];    // e^{-2pi i k x/64}
__device__ float2 g_Ez [KZM*NZ];   // e^{-2pi i f z/40}, f = k<8?k:k+5
__device__ float2 g_EyR[KYM*NY];   // e^{-2pi i f y/64}, f = k<16?k:k+1
__device__ float2 g_IEx[KM*NX];    // (1/64) e^{+2pi i k x/64}
__device__ float2 g_IBz[KZM*NZ];   // (w/40) e^{+2pi i f z/40}
__device__ float2 g_IBy[KYM*NY];   // (w/64) e^{+2pi i f y/64}

// ---------------- scratch ----------------
__device__ float2 g_Qx[(size_t)NB*KM*NY*NZ*C];    // [b][kx][y][z][i]
__device__ float2 g_P1[(size_t)NB*NX*NY*KZM*C];   // [b][x][y][kz][i]
__device__ float2 g_F [(size_t)512*160*C];        // [mode][row][c]  (max: xy 512x160)
__device__ float2 g_R [(size_t)NB*64*NZ*KM*C];    // [b][u][z or y][k][o]
__device__ float  g_acc[(size_t)NB*NX*NY*NZ*C];   // [b][x][y][z][o]

// ---------------- init twiddles ----------------
__global__ void __launch_bounds__(256) k_init() {
    int tid = threadIdx.x;
    for (int t = tid; t < KM*NX; t += blockDim.x) {
        int k = t / NX, n = t % NX;
        int m = (k*n) % NX;
        float s, c;
        sincospif(-2.0f * m / NX, &s, &c);
        g_Ex[t] = make_float2(c, s);
        sincospif( 2.0f * m / NX, &s, &c);
        g_IEx[t] = make_float2(c / NX, s / NX);
    }
    for (int t = tid; t < KZM*NZ; t += blockDim.x) {
        int k = t / NZ, n = t % NZ;
        int f = (k < 8) ? k : k + 5;          // {0..7, 13..20}
        int m = (f*n) % NZ;
        float s, c;
        sincospif(-2.0f * m / NZ, &s, &c);
        g_Ez[t] = make_float2(c, s);
        float w = (f == 0 || f == NZ/2) ? 1.f : 2.f;
        sincospif( 2.0f * m / NZ, &s, &c);
        g_IBz[t] = make_float2(c * w / NZ, s * w / NZ);
    }
    for (int t = tid; t < KYM*NY; t += blockDim.x) {
        int k = t / NY, n = t % NY;
        int f = (k < 16) ? k : k + 1;         // {0..15, 17..32}
        int m = (f*n) % NY;
        float s, c;
        sincospif(-2.0f * m / NY, &s, &c);
        g_EyR[t] = make_float2(c, s);
        float w = (f == 0 || f == NY/2) ? 1.f : 2.f;
        sincospif( 2.0f * m / NY, &s, &c);
        g_IBy[t] = make_float2(c * w / NY, s * w / NY);
    }
}

// ---------------- 1x1 conv (init acc) ----------------
__global__ void __launch_bounds__(640) k_conv(const float* __restrict__ x,
                                              const float* __restrict__ w,
                                              const float* __restrict__ bias) {
    __shared__ float xs[NZ*C];
    __shared__ float Wt[C*C];   // Wt[i*32+o] = w[o*32+i]
    __shared__ float bs[C];
    int y = blockIdx.x, xx = blockIdx.y, b = blockIdx.z;
    int tid = threadIdx.x;  // 640
    const float* xr = x + (((size_t)(b*NX+xx)*NY + y) * NZ) * C;
    for (int t = tid; t < NZ*C; t += 640) xs[t] = xr[t];
    for (int t = tid; t < C*C;  t += 640) Wt[t] = w[(t % C) * C + (t / C)];
    if (tid < C) bs[tid] = bias[tid];
    __syncthreads();
    int o = tid & 31, zz = tid >> 5;   // zz in [0,20)
    float* ar = g_acc + (((size_t)(b*NX+xx)*NY + y) * NZ) * C;
    for (int rep = 0; rep < 2; rep++) {
        int z = zz + rep * 20;
        float v = bs[o];
        #pragma unroll
        for (int i = 0; i < C; i++) v += xs[z*C + i] * Wt[i*C + o];
        ar[z*C + o] = v;
    }
}

// ---------------- truncated fft over x ----------------
__global__ void __launch_bounds__(512) k_fftx(const float* __restrict__ x) {
    __shared__ float  xs[NX*C];
    __shared__ float2 tw[KM*NX];
    int z = blockIdx.x, y = blockIdx.y, b = blockIdx.z;
    int tid = threadIdx.x;  // 512
    for (int t = tid; t < NX*C; t += 512) {
        int xx = t / C, i = t % C;
        xs[t] = x[((((size_t)b*NX + xx)*NY + y)*NZ + z)*C + i];
    }
    for (int t = tid; t < KM*NX; t += 512) tw[t] = g_Ex[t];
    __syncthreads();
    int i = tid & 31, k = tid >> 5;
    float re = 0.f, im = 0.f;
    #pragma unroll
    for (int xx = 0; xx < NX; xx++) {
        float v = xs[xx*C + i];
        float2 e = tw[k*NX + xx];
        re += v * e.x; im += v * e.y;
    }
    g_Qx[((((size_t)b*KM + k)*NY + y)*NZ + z)*C + i] = make_float2(re, im);
}

// ---------------- truncated rfft over z ----------------
__global__ void __launch_bounds__(512) k_rfftz(const float* __restrict__ x) {
    __shared__ float  xs[NZ*C];
    __shared__ float2 tw[KZM*NZ];
    int y = blockIdx.x, xx = blockIdx.y, b = blockIdx.z;
    int tid = threadIdx.x;  // 512
    const float* xr = x + (((size_t)(b*NX+xx)*NY + y) * NZ) * C;
    for (int t = tid; t < NZ*C;   t += 512) xs[t] = xr[t];
    for (int t = tid; t < KZM*NZ; t += 512) tw[t] = g_Ez[t];
    __syncthreads();
    int i = tid & 31, k = tid >> 5;
    float re = 0.f, im = 0.f;
    #pragma unroll
    for (int z = 0; z < NZ; z++) {
        float v = xs[z*C + i];
        float2 e = tw[k*NZ + z];
        re += v * e.x; im += v * e.y;
    }
    g_P1[((((size_t)(b*NX+xx)*NY + y)*KZM) + k)*C + i] = make_float2(re, im);
}

// ---------------- xz: z-transform of Qx ----------------
__global__ void __launch_bounds__(512) k_zfftQ() {
    __shared__ float2 qs[NZ*C];
    __shared__ float2 tw[KZM*NZ];
    int y = blockIdx.x, kx = blockIdx.y, b = blockIdx.z;
    int tid = threadIdx.x;  // 512
    const float2* qr = g_Qx + (((size_t)(b*KM + kx)*NY + y) * NZ) * C;
    for (int t = tid; t < NZ*C;   t += 512) qs[t] = qr[t];
    for (int t = tid; t < KZM*NZ; t += 512) tw[t] = g_Ez[t];
    __syncthreads();
    int i = tid & 31, kz = tid >> 5;
    float re = 0.f, im = 0.f;
    #pragma unroll
    for (int z = 0; z < NZ; z++) {
        float2 a = qs[z*C + i];
        float2 e = tw[kz*NZ + z];
        re += a.x*e.x - a.y*e.y;
        im += a.x*e.y + a.y*e.x;
    }
    int m = kx*KZM + kz;
    g_F[((size_t)m*(NB*NY) + b*NY + y)*C + i] = make_float2(re, im);
}

// ---------------- xy: y-transform (real axis, 32 modes) of Qx ----------------
__global__ void __launch_bounds__(1024) k_yfftQ() {
    __shared__ float2 qs[NY*C];
    __shared__ float2 tw[KYM*NY];
    int z = blockIdx.x, kx = blockIdx.y, b = blockIdx.z;
    int tid = threadIdx.x;  // 1024
    for (int t = tid; t < NY*C; t += 1024) {
        int y = t / C, i = t % C;
        qs[t] = g_Qx[((((size_t)b*KM + kx)*NY + y)*NZ + z)*C + i];
    }
    for (int t = tid; t < KYM*NY; t += 1024) tw[t] = g_EyR[t];
    __syncthreads();
    int i = tid & 31, ky = tid >> 5;   // ky in [0,32)
    float re = 0.f, im = 0.f;
    #pragma unroll
    for (int y = 0; y < NY; y++) {
        float2 a = qs[y*C + i];
        float2 e = tw[ky*NY + y];
        re += a.x*e.x - a.y*e.y;
        im += a.x*e.y + a.y*e.x;
    }
    int m = kx*KYM + ky;
    g_F[((size_t)m*(NB*NZ) + b*NZ + z)*C + i] = make_float2(re, im);
}

// ---------------- yz: y-transform (complex axis, 16 modes) of P1 ----------------
__global__ void __launch_bounds__(512) k_yfftP() {
    __shared__ float2 ps[NY*C];
    __shared__ float2 tw[KM*NY];
    int kz = blockIdx.x, xx = blockIdx.y, b = blockIdx.z;
    int tid = threadIdx.x;  // 512
    for (int t = tid; t < NY*C; t += 512) {
        int y = t / C, i = t % C;
        ps[t] = g_P1[((((size_t)(b*NX+xx)*NY + y)*KZM) + kz)*C + i];
    }
    for (int t = tid; t < KM*NY; t += 512) tw[t] = g_Ex[t];
    __syncthreads();
    int i = tid & 31, ky = tid >> 5;
    float re = 0.f, im = 0.f;
    #pragma unroll
    for (int y = 0; y < NY; y++) {
        float2 a = ps[y*C + i];
        float2 e = tw[ky*NY + y];
        re += a.x*e.x - a.y*e.y;
        im += a.x*e.y + a.y*e.x;
    }
    int m = ky*KZM + kz;
    g_F[((size_t)m*(NB*NX) + b*NX + xx)*C + i] = make_float2(re, im);
}

// ---------------- per-mode complex 32x32 channel mix (in place) ----------------
__global__ void __launch_bounds__(1024) k_mix(const float* __restrict__ fw,
                                              const float* __restrict__ fw2,
                                              int rows, int D) {
    __shared__ float2 Ws[C*C];
    __shared__ float2 Fs[32*C];
    int m = blockIdx.x;
    int tid = threadIdx.x;   // 1024
    int mpx = 2 * D;
    int kx = m / mpx, km = m % mpx;
    const float* W = (km < D) ? fw : fw2;
    int kk = (km < D) ? km : km - D;
    {
        int i = tid >> 5, o = tid & 31;
        size_t base = ((((size_t)i*C + o)*KM + kx)*D + kk) * 2;
        Ws[i*C + o] = make_float2(W[base], W[base + 1]);
    }
    __syncthreads();
    int o = tid & 31, rr = tid >> 5;
    int nch = rows / 32;
    for (int ch = 0; ch < nch; ch++) {
        size_t idx = ((size_t)m*rows + ch*32 + rr)*C + o;
        Fs[rr*C + o] = g_F[idx];
        __syncthreads();
        float re = 0.f, im = 0.f;
        #pragma unroll
        for (int i = 0; i < C; i++) {
            float2 a = Fs[rr*C + i];
            float2 w = Ws[i*C + o];
            re += a.x*w.x - a.y*w.y;
            im += a.x*w.y + a.y*w.x;
        }
        __syncthreads();
        g_F[idx] = make_float2(re, im);
    }
}

// ---------------- inverse over z (16 modes -> 40), complex ----------------
__global__ void __launch_bounds__(640) k_invZ() {
    __shared__ float2 Gs[KZM*C];
    int u = blockIdx.x, kc = blockIdx.y, b = blockIdx.z;
    int tid = threadIdx.x;   // 640
    if (tid < KZM*C) {
        int kz = tid >> 5, o = tid & 31;
        Gs[tid] = g_F[((size_t)(kc*KZM + kz)*(NB*64) + b*64 + u)*C + o];
    }
    __syncthreads();
    int o = tid & 31, zz = tid >> 5;   // [0,20)
    for (int rep = 0; rep < 2; rep++) {
        int z = zz + rep * 20;
        float re = 0.f, im = 0.f;
        #pragma unroll
        for (int kz = 0; kz < KZM; kz++) {
            float2 g = Gs[kz*C + o];
            float2 e = g_IBz[kz*NZ + z];
            re += g.x*e.x - g.y*e.y;
            im += g.x*e.y + g.y*e.x;
        }
        g_R[(((size_t)(b*64 + u)*NZ + z)*KM + kc)*C + o] = make_float2(re, im);
    }
}

// ---------------- inverse over y real axis (32 modes -> 64), complex (xy) ----------------
__global__ void __launch_bounds__(1024) k_invY() {
    __shared__ float2 Gs[KYM*C];
    int z = blockIdx.x, kx = blockIdx.y, b = blockIdx.z;
    int tid = threadIdx.x;   // 1024
    {
        int ky = tid >> 5, o = tid & 31;
        Gs[tid] = g_F[((size_t)(kx*KYM + ky)*(NB*NZ) + b*NZ + z)*C + o];
    }
    __syncthreads();
    int o = tid & 31, yy = tid >> 5;   // [0,32)
    for (int rep = 0; rep < 2; rep++) {
        int y = yy + rep * 32;
        float re = 0.f, im = 0.f;
        #pragma unroll
        for (int ky = 0; ky < KYM; ky++) {
            float2 g = Gs[ky*C + o];
            float2 e = g_IBy[ky*NY + y];
            re += g.x*e.x - g.y*e.y;
            im += g.x*e.y + g.y*e.x;
        }
        g_R[(((size_t)(b*NZ + z)*NY + y)*KM + kx)*C + o] = make_float2(re, im);
    }
}

// ---------------- inverse over complex axis (16 modes -> 64), Re(), accumulate ----------------
template <int BR>
__global__ void __launch_bounds__(1024) k_invAcc() {
    __shared__ float2 Rs[KM*C];
    int tid = threadIdx.x;   // 1024
    int b = blockIdx.z;
    size_t rrow, obase, ostride;
    if (BR == 0) {            // xz : n' = x ; fixed (y,z)
        int z = blockIdx.x, y = blockIdx.y;
        rrow = ((size_t)(b*NY + y))*NZ + z;
        obase = (((size_t)(b*NX + 0)*NY + y)*NZ + z)*C;
        ostride = (size_t)NY*NZ*C;
    } else if (BR == 1) {     // yz : n' = y ; fixed (x,z)
        int z = blockIdx.x, xx = blockIdx.y;
        rrow = ((size_t)(b*NX + xx))*NZ + z;
        obase = (((size_t)(b*NX + xx)*NY + 0)*NZ + z)*C;
        ostride = (size_t)NZ*C;
    } else {                  // xy : n' = x ; fixed (y,z); R rows (b*NZ+z)*NY+y
        int y = blockIdx.x, z = blockIdx.y;
        rrow = ((size_t)(b*NZ + z))*NY + y;
        obase = (((size_t)(b*NX + 0)*NY + y)*NZ + z)*C;
        ostride = (size_t)NY*NZ*C;
    }
    if (tid < KM*C) Rs[tid] = g_R[rrow*(KM*C) + tid];
    __syncthreads();
    int o = tid & 31, nn = tid >> 5;   // [0,32)
    for (int rep = 0; rep < 2; rep++) {
        int n = nn + rep * 32;
        float s = 0.f;
        #pragma unroll
        for (int k = 0; k < KM; k++) {
            float2 r = Rs[k*C + o];
            float2 e = g_IEx[k*NX + n];
            s += r.x*e.x - r.y*e.y;
        }
        g_acc[obase + (size_t)n*ostride + o] += s;
    }
}

// ---------------- feedforward: out = relu(acc @ w0^T + b0) @ w1^T + b1 ----------------
__global__ void __launch_bounds__(256) k_ff(const float* __restrict__ w0,
                                            const float* __restrict__ b0,
                                            const float* __restrict__ w1,
                                            const float* __restrict__ b1,
                                            float* __restrict__ out) {
    __shared__ float w0t[C*64];   // [i][h]
    __shared__ float w1t[64*C];   // [h][o]
    __shared__ float b0s[64], b1s[C];
    __shared__ float as[8][C];
    __shared__ float h1s[8][64];
    int tid = threadIdx.x;   // 256
    for (int t = tid; t < C*64; t += 256) { int i = t / 64, h = t % 64; w0t[t] = w0[h*C + i]; }
    for (int t = tid; t < 64*C; t += 256) { int h = t / C,  o = t % C;  w1t[t] = w1[o*64 + h]; }
    if (tid < 64) b0s[tid] = b0[tid];
    if (tid < C)  b1s[tid] = b1[tid];
    __syncthreads();
    int lane = tid & 31, w = tid >> 5;
    const int TPW = 32;
    size_t t0 = ((size_t)blockIdx.x * 8 + w) * TPW;
    for (int j = 0; j < TPW; j++) {
        size_t t = t0 + j;
        as[w][lane] = g_acc[t*C + lane];
        __syncwarp();
        float h1a = b0s[lane], h1b = b0s[lane + 32];
        #pragma unroll
        for (int i = 0; i < C; i++) {
            float a = as[w][i];
            h1a += a * w0t[i*64 + lane];
            h1b += a * w0t[i*64 + lane + 32];
        }
        h1a = fmaxf(h1a, 0.f); h1b = fmaxf(h1b, 0.f);
        h1s[w][lane] = h1a; h1s[w][lane + 32] = h1b;
        __syncwarp();
        float v = b1s[lane];
        #pragma unroll
        for (int h = 0; h < 64; h++) v += h1s[w][h] * w1t[h*C + lane];
        out[t*C + lane] = v;
        __syncwarp();
    }
}

extern "C" void kernel_launch(void* const* d_in, const int* in_sizes, int n_in,
                              void* d_out, int out_size) {
    const float* x      = (const float*)d_in[0];
    const float* w      = (const float*)d_in[1];
    const float* wb     = (const float*)d_in[2];
    const float* fw_xy  = (const float*)d_in[3];
    const float* fw_yz  = (const float*)d_in[4];
    const float* fw_xz  = (const float*)d_in[5];
    const float* fw2_xy = (const float*)d_in[6];
    const float* fw2_yz = (const float*)d_in[7];
    const float* fw2_xz = (const float*)d_in[8];
    const float* ffw0   = (const float*)d_in[9];
    const float* ffb0   = (const float*)d_in[10];
    const float* ffw1   = (const float*)d_in[11];
    const float* ffb1   = (const float*)d_in[12];
    float* out = (float*)d_out;

    k_init<<<1, 256>>>();
    k_conv<<<dim3(NY, NX, NB), 640>>>(x, w, wb);

    // shared forward fft over x (feeds xz + xy)
    k_fftx<<<dim3(NZ, NY, NB), 512>>>(x);

    // ---- xz branch ----
    k_zfftQ<<<dim3(NY, KM, NB), 512>>>();
    k_mix<<<256, 1024>>>(fw_xz, fw2_xz, NB*NY, 8);
    k_invZ<<<dim3(NY, KM, NB), 640>>>();
    k_invAcc<0><<<dim3(NZ, NY, NB), 1024>>>();

    // ---- xy branch ----
    k_yfftQ<<<dim3(NZ, KM, NB), 1024>>>();
    k_mix<<<512, 1024>>>(fw_xy, fw2_xy, NB*NZ, 16);
    k_invY<<<dim3(NZ, KM, NB), 1024>>>();
    k_invAcc<2><<<dim3(NY, NZ, NB), 1024>>>();

    // ---- yz branch ----
    k_rfftz<<<dim3(NY, NX, NB), 512>>>(x);
    k_yfftP<<<dim3(KZM, NX, NB), 512>>>();
    k_mix<<<256, 1024>>>(fw_yz, fw2_yz, NB*NX, 8);
    k_invZ<<<dim3(NX, KM, NB), 640>>>();
    k_invAcc<1><<<dim3(NZ, NX, NB), 1024>>>();

    // ---- feedforward ----
    k_ff<<<2560, 256>>>(ffw0, ffb0, ffw1, ffb1, out);
}

// round 5
// speedup vs baseline: 1.8440x; 1.8440x over previous
#include <cuda_runtime.h>
#include <cstdint>

#define NB 4
#define NX 64
#define NY 64
#define NZ 40
#define C  32
#define KM 16    // complex-axis kept modes (x for xz/xy, y for yz)
#define KZM 16   // z real-axis kept modes  {0..7} u {13..20}
#define KYM 32   // y real-axis kept modes  {0..15} u {17..32}

// ================= compile-time trig (twiddles become FFMA immediates) ======
constexpr double D_PI = 3.141592653589793238462643383279502884;

constexpr double tsin_(double x) {   // |x| <= pi, Taylor
    double x2 = x * x, t = x, s = x;
    for (int n = 1; n <= 13; n++) { t *= -x2 / ((2.0*n) * (2.0*n + 1.0)); s += t; }
    return s;
}
constexpr double tcos_(double x) {
    double x2 = x * x, t = 1.0, s = 1.0;
    for (int n = 1; n <= 13; n++) { t *= -x2 / ((2.0*n - 1.0) * (2.0*n)); s += t; }
    return s;
}
constexpr double ang_(int m, int N) {   // 2*pi*m/N reduced to [-pi, pi]
    int mm = m % N;
    if (mm > N / 2) mm -= N;
    return 2.0 * D_PI * mm / N;
}

// forward x / complex-y axis: e^{-2pi i k n / 64}, k in [0,16)
struct FXT { float c[16][64]; float s[16][64]; };
constexpr FXT mkFX() {
    FXT t{};
    for (int k = 0; k < 16; k++)
        for (int n = 0; n < 64; n++) {
            double a = ang_(k * n, 64);
            t.c[k][n] = (float)tcos_(a);
            t.s[k][n] = (float)(-tsin_(a));
        }
    return t;
}
__device__ constexpr FXT FX = mkFX();

// forward z axis: e^{-2pi i f(k) n / 40}, f = k<8 ? k : k+5
struct FZT { float c[16][40]; float s[16][40]; };
constexpr FZT mkFZ() {
    FZT t{};
    for (int k = 0; k < 16; k++) {
        int f = (k < 8) ? k : k + 5;
        for (int n = 0; n < 40; n++) {
            double a = ang_(f * n, 40);
            t.c[k][n] = (float)tcos_(a);
            t.s[k][n] = (float)(-tsin_(a));
        }
    }
    return t;
}
__device__ constexpr FZT FZ = mkFZ();

// forward y real-axis (xy branch): e^{-2pi i f(k) n / 64}, f = k<16 ? k : k+1
struct FYT { float c[32][64]; float s[32][64]; };
constexpr FYT mkFY() {
    FYT t{};
    for (int k = 0; k < 32; k++) {
        int f = (k < 16) ? k : k + 1;
        for (int n = 0; n < 64; n++) {
            double a = ang_(f * n, 64);
            t.c[k][n] = (float)tcos_(a);
            t.s[k][n] = (float)(-tsin_(a));
        }
    }
    return t;
}
__device__ constexpr FYT FY = mkFY();

// inverse complex axis: (1/64) e^{+2pi i k n/64}
struct IXT { float c[16][64]; float s[16][64]; };
constexpr IXT mkIX() {
    IXT t{};
    for (int k = 0; k < 16; k++)
        for (int n = 0; n < 64; n++) {
            double a = ang_(k * n, 64);
            t.c[k][n] = (float)(tcos_(a) / 64.0);
            t.s[k][n] = (float)(tsin_(a) / 64.0);
        }
    return t;
}
__device__ constexpr IXT IX = mkIX();

// inverse z real axis: (w/40) e^{+2pi i f(k) n/40}, w=1 for f=0 or 20 else 2
struct IZT { float c[16][40]; float s[16][40]; };
constexpr IZT mkIZ() {
    IZT t{};
    for (int k = 0; k < 16; k++) {
        int f = (k < 8) ? k : k + 5;
        double w = (f == 0 || f == 20) ? 1.0 : 2.0;
        for (int n = 0; n < 40; n++) {
            double a = ang_(f * n, 40);
            t.c[k][n] = (float)(tcos_(a) * w / 40.0);
            t.s[k][n] = (float)(tsin_(a) * w / 40.0);
        }
    }
    return t;
}
__device__ constexpr IZT IZ = mkIZ();

// inverse y real axis: (w/64) e^{+2pi i f(k) n/64}, f = k<16?k:k+1, w=1 for f=0 or 32
struct IYT { float c[32][64]; float s[32][64]; };
constexpr IYT mkIY() {
    IYT t{};
    for (int k = 0; k < 32; k++) {
        int f = (k < 16) ? k : k + 1;
        double w = (f == 0 || f == 32) ? 1.0 : 2.0;
        for (int n = 0; n < 64; n++) {
            double a = ang_(f * n, 64);
            t.c[k][n] = (float)(tcos_(a) * w / 64.0);
            t.s[k][n] = (float)(tsin_(a) * w / 64.0);
        }
    }
    return t;
}
__device__ constexpr IYT IY = mkIY();

// ================= scratch =================
__device__ float2 g_Qx[(size_t)NB*KM*NY*NZ*C];    // [b][kx][y][z][i]
__device__ float2 g_P1[(size_t)NB*NX*NY*KZM*C];   // [b][x][y][kz][i]
__device__ float2 g_F [(size_t)512*160*C];        // [mode][row][c]
__device__ float2 g_R [(size_t)NB*64*NZ*KM*C];    // [b][u][pos][k][o]
__device__ float  g_acc[(size_t)NB*NX*NY*NZ*C];   // [b][x][y][z][o]

// ================= 1x1 conv (init acc) =================
__global__ void __launch_bounds__(640) k_conv(const float* __restrict__ x,
                                              const float* __restrict__ w,
                                              const float* __restrict__ bias) {
    __shared__ float xs[NZ*C];
    __shared__ float Wt[C*C];
    __shared__ float bs[C];
    int y = blockIdx.x, xx = blockIdx.y, b = blockIdx.z;
    int tid = threadIdx.x;
    const float* xr = x + (((size_t)(b*NX+xx)*NY + y) * NZ) * C;
    for (int t = tid; t < NZ*C; t += 640) xs[t] = xr[t];
    for (int t = tid; t < C*C;  t += 640) Wt[t] = w[(t % C) * C + (t / C)];
    if (tid < C) bs[tid] = bias[tid];
    __syncthreads();
    int o = tid & 31, zz = tid >> 5;
    float* ar = g_acc + (((size_t)(b*NX+xx)*NY + y) * NZ) * C;
    for (int rep = 0; rep < 2; rep++) {
        int z = zz + rep * 20;
        float v = bs[o];
        #pragma unroll
        for (int i = 0; i < C; i++) v += xs[z*C + i] * Wt[i*C + o];
        ar[z*C + o] = v;
    }
}

// ================= forward x DFT (8 modes from M0), imm twiddles =============
template<int M0>
__global__ void __launch_bounds__(256) k_fftx(const float* __restrict__ x) {
    int w = threadIdx.x >> 5, i = threadIdx.x & 31;
    int z = blockIdx.x * 8 + w;
    int y = blockIdx.y, b = blockIdx.z;
    const float* px = x + (((size_t)b*NX*NY + y)*NZ + z)*C + i;
    float2 acc[8];
    #pragma unroll
    for (int k = 0; k < 8; k++) acc[k] = make_float2(0.f, 0.f);
    #pragma unroll
    for (int xx = 0; xx < NX; xx++) {
        float v = px[(size_t)xx*NY*NZ*C];
        #pragma unroll
        for (int kk = 0; kk < 8; kk++) {
            acc[kk].x = fmaf(v, FX.c[M0+kk][xx], acc[kk].x);
            acc[kk].y = fmaf(v, FX.s[M0+kk][xx], acc[kk].y);
        }
    }
    #pragma unroll
    for (int kk = 0; kk < 8; kk++)
        g_Qx[((((size_t)b*KM + M0+kk)*NY + y)*NZ + z)*C + i] = acc[kk];
}

// ================= forward z rDFT (16 modes), imm twiddles ====================
__global__ void __launch_bounds__(256) k_rfftz(const float* __restrict__ x) {
    int w = threadIdx.x >> 5, i = threadIdx.x & 31;
    int y = blockIdx.x * 8 + w;
    int xx = blockIdx.y, b = blockIdx.z;
    const float* px = x + (((size_t)(b*NX+xx)*NY + y) * NZ) * C + i;
    float2 acc[16];
    #pragma unroll
    for (int k = 0; k < 16; k++) acc[k] = make_float2(0.f, 0.f);
    #pragma unroll
    for (int z = 0; z < NZ; z++) {
        float v = px[(size_t)z*C];
        #pragma unroll
        for (int k = 0; k < 16; k++) {
            acc[k].x = fmaf(v, FZ.c[k][z], acc[k].x);
            acc[k].y = fmaf(v, FZ.s[k][z], acc[k].y);
        }
    }
    float2* q = g_P1 + (((size_t)(b*NX+xx)*NY + y) * KZM) * C + i;
    #pragma unroll
    for (int k = 0; k < 16; k++) q[(size_t)k*C] = acc[k];
}

// ================= xz: z DFT of Qx (8 modes from M0), complex =================
template<int M0>
__global__ void __launch_bounds__(256) k_zfftQ() {
    int w = threadIdx.x >> 5, i = threadIdx.x & 31;
    int y = blockIdx.x * 8 + w;
    int kx = blockIdx.y, b = blockIdx.z;
    const float2* q = g_Qx + (((size_t)(b*KM+kx)*NY + y) * NZ) * C + i;
    float2 acc[8];
    #pragma unroll
    for (int k = 0; k < 8; k++) acc[k] = make_float2(0.f, 0.f);
    #pragma unroll
    for (int z = 0; z < NZ; z++) {
        float2 a = q[(size_t)z*C];
        #pragma unroll
        for (int kk = 0; kk < 8; kk++) {
            float cc = FZ.c[M0+kk][z], ss = FZ.s[M0+kk][z];
            acc[kk].x = fmaf(a.x, cc, acc[kk].x);
            acc[kk].x = fmaf(a.y, -ss, acc[kk].x);
            acc[kk].y = fmaf(a.x, ss, acc[kk].y);
            acc[kk].y = fmaf(a.y, cc, acc[kk].y);
        }
    }
    #pragma unroll
    for (int kk = 0; kk < 8; kk++) {
        int m = kx*KZM + M0 + kk;
        g_F[((size_t)m*(NB*NY) + b*NY + y)*C + i] = acc[kk];
    }
}

// ================= xy: y DFT (real axis, 8 of 32 modes from M0) ===============
template<int M0>
__global__ void __launch_bounds__(256) k_yfftQ() {
    int w = threadIdx.x >> 5, i = threadIdx.x & 31;
    int z = blockIdx.x * 8 + w;
    int kx = blockIdx.y, b = blockIdx.z;
    const float2* q = g_Qx + (((size_t)(b*KM+kx)*NY) * NZ + z) * C + i;
    float2 acc[8];
    #pragma unroll
    for (int k = 0; k < 8; k++) acc[k] = make_float2(0.f, 0.f);
    #pragma unroll
    for (int y = 0; y < NY; y++) {
        float2 a = q[(size_t)y*NZ*C];
        #pragma unroll
        for (int kk = 0; kk < 8; kk++) {
            float cc = FY.c[M0+kk][y], ss = FY.s[M0+kk][y];
            acc[kk].x = fmaf(a.x, cc, acc[kk].x);
            acc[kk].x = fmaf(a.y, -ss, acc[kk].x);
            acc[kk].y = fmaf(a.x, ss, acc[kk].y);
            acc[kk].y = fmaf(a.y, cc, acc[kk].y);
        }
    }
    #pragma unroll
    for (int kk = 0; kk < 8; kk++) {
        int m = kx*KYM + M0 + kk;
        g_F[((size_t)m*(NB*NZ) + b*NZ + z)*C + i] = acc[kk];
    }
}

// ================= yz: y DFT of P1 (complex axis, 8 of 16 modes) ==============
template<int M0>
__global__ void __launch_bounds__(256) k_yfftP() {
    int w = threadIdx.x >> 5, i = threadIdx.x & 31;
    int kz = blockIdx.x * 8 + w;
    int xx = blockIdx.y, b = blockIdx.z;
    const float2* p = g_P1 + (((size_t)(b*NX+xx)*NY) * KZM + kz) * C + i;
    float2 acc[8];
    #pragma unroll
    for (int k = 0; k < 8; k++) acc[k] = make_float2(0.f, 0.f);
    #pragma unroll
    for (int y = 0; y < NY; y++) {
        float2 a = p[(size_t)y*KZM*C];
        #pragma unroll
        for (int kk = 0; kk < 8; kk++) {
            float cc = FX.c[M0+kk][y], ss = FX.s[M0+kk][y];
            acc[kk].x = fmaf(a.x, cc, acc[kk].x);
            acc[kk].x = fmaf(a.y, -ss, acc[kk].x);
            acc[kk].y = fmaf(a.x, ss, acc[kk].y);
            acc[kk].y = fmaf(a.y, cc, acc[kk].y);
        }
    }
    #pragma unroll
    for (int kk = 0; kk < 8; kk++) {
        int m = (M0+kk)*KZM + kz;
        g_F[((size_t)m*(NB*NX) + b*NX + xx)*C + i] = acc[kk];
    }
}

// ================= per-mode complex 32x32 channel mix (in place) ==============
__global__ void __launch_bounds__(1024) k_mix(const float* __restrict__ fw,
                                              const float* __restrict__ fw2,
                                              int rows, int D) {
    __shared__ float2 Ws[C*C];
    __shared__ float2 Fs[32*C];
    int m = blockIdx.x;
    int tid = threadIdx.x;
    int mpx = 2 * D;
    int kx = m / mpx, km = m % mpx;
    const float* W = (km < D) ? fw : fw2;
    int kk = (km < D) ? km : km - D;
    {
        int i = tid >> 5, o = tid & 31;
        size_t base = ((((size_t)i*C + o)*KM + kx)*D + kk) * 2;
        Ws[i*C + o] = make_float2(W[base], W[base + 1]);
    }
    __syncthreads();
    int o = tid & 31, rr = tid >> 5;
    int nch = rows / 32;
    for (int ch = 0; ch < nch; ch++) {
        size_t idx = ((size_t)m*rows + ch*32 + rr)*C + o;
        Fs[rr*C + o] = g_F[idx];
        __syncthreads();
        float re = 0.f, im = 0.f;
        #pragma unroll
        for (int i = 0; i < C; i++) {
            float2 a = Fs[rr*C + i];
            float2 w = Ws[i*C + o];
            re += a.x*w.x - a.y*w.y;
            im += a.x*w.y + a.y*w.x;
        }
        __syncthreads();
        g_F[idx] = make_float2(re, im);
    }
}

// ================= inverse over z (16 modes -> 40 z), imm twiddles ============
template<int Z0>
__device__ __forceinline__ void invZ_body(int b, int kc, int u, int o) {
    float2 acc[8];
    #pragma unroll
    for (int j = 0; j < 8; j++) acc[j] = make_float2(0.f, 0.f);
    #pragma unroll
    for (int kz = 0; kz < KZM; kz++) {
        float2 g = g_F[((size_t)(kc*KZM + kz)*(NB*64) + b*64 + u)*C + o];
        #pragma unroll
        for (int j = 0; j < 8; j++) {
            float cc = IZ.c[kz][Z0+j], ss = IZ.s[kz][Z0+j];
            acc[j].x = fmaf(g.x, cc, acc[j].x);
            acc[j].x = fmaf(g.y, -ss, acc[j].x);
            acc[j].y = fmaf(g.x, ss, acc[j].y);
            acc[j].y = fmaf(g.y, cc, acc[j].y);
        }
    }
    #pragma unroll
    for (int j = 0; j < 8; j++)
        g_R[(((size_t)(b*64 + u)*NZ + Z0 + j)*KM + kc)*C + o] = acc[j];
}
__global__ void __launch_bounds__(320) k_invZ() {
    int w = threadIdx.x >> 5, o = threadIdx.x & 31;
    int u = blockIdx.x * 2 + (w / 5);
    int slot = w % 5;
    int kc = blockIdx.y, b = blockIdx.z;
    switch (slot) {
        case 0: invZ_body<0 >(b, kc, u, o); break;
        case 1: invZ_body<8 >(b, kc, u, o); break;
        case 2: invZ_body<16>(b, kc, u, o); break;
        case 3: invZ_body<24>(b, kc, u, o); break;
        default: invZ_body<32>(b, kc, u, o); break;
    }
}

// ================= inverse over y real axis (32 modes -> 64 y), xy ============
template<int Y0>
__device__ __forceinline__ void invY_body(int b, int kx, int z, int o) {
    float2 acc[8];
    #pragma unroll
    for (int j = 0; j < 8; j++) acc[j] = make_float2(0.f, 0.f);
    #pragma unroll
    for (int ky = 0; ky < KYM; ky++) {
        float2 g = g_F[((size_t)(kx*KYM + ky)*(NB*NZ) + b*NZ + z)*C + o];
        #pragma unroll
        for (int j = 0; j < 8; j++) {
            float cc = IY.c[ky][Y0+j], ss = IY.s[ky][Y0+j];
            acc[j].x = fmaf(g.x, cc, acc[j].x);
            acc[j].x = fmaf(g.y, -ss, acc[j].x);
            acc[j].y = fmaf(g.x, ss, acc[j].y);
            acc[j].y = fmaf(g.y, cc, acc[j].y);
        }
    }
    #pragma unroll
    for (int j = 0; j < 8; j++)
        g_R[(((size_t)(b*NZ + z)*NY + Y0 + j)*KM + kx)*C + o] = acc[j];
}
__global__ void __launch_bounds__(512) k_invY() {
    int w = threadIdx.x >> 5, o = threadIdx.x & 31;
    int z = blockIdx.x * 2 + (w >> 3);
    int slot = w & 7;
    int kx = blockIdx.y, b = blockIdx.z;
    switch (slot) {
        case 0: invY_body<0 >(b, kx, z, o); break;
        case 1: invY_body<8 >(b, kx, z, o); break;
        case 2: invY_body<16>(b, kx, z, o); break;
        case 3: invY_body<24>(b, kx, z, o); break;
        case 4: invY_body<32>(b, kx, z, o); break;
        case 5: invY_body<40>(b, kx, z, o); break;
        case 6: invY_body<48>(b, kx, z, o); break;
        default: invY_body<56>(b, kx, z, o); break;
    }
}

// ================= inverse complex axis (16 modes -> 64), Re(), += ============
template<int N0>
__device__ __forceinline__ void invAcc_body(size_t rrow, size_t obase, size_t ostride, int o) {
    float acc[8];
    #pragma unroll
    for (int j = 0; j < 8; j++) acc[j] = 0.f;
    #pragma unroll
    for (int k = 0; k < KM; k++) {
        float2 r = g_R[rrow*(KM*C) + (size_t)k*C + o];
        #pragma unroll
        for (int j = 0; j < 8; j++) {
            acc[j] = fmaf(r.x, IX.c[k][N0+j], acc[j]);
            acc[j] = fmaf(r.y, -IX.s[k][N0+j], acc[j]);
        }
    }
    #pragma unroll
    for (int j = 0; j < 8; j++)
        g_acc[obase + (size_t)(N0+j)*ostride + o] += acc[j];
}
template<int BR>
__global__ void __launch_bounds__(512) k_invAcc() {
    int w = threadIdx.x >> 5, o = threadIdx.x & 31;
    int r = w >> 3, slot = w & 7;
    int b = blockIdx.z;
    size_t rrow, obase, ostride;
    if (BR == 0) {            // xz : n' = x ; fixed (y,z)
        int z = blockIdx.x, y = blockIdx.y*2 + r;
        rrow = ((size_t)(b*NY + y))*NZ + z;
        obase = (((size_t)b*NX*NY + y)*NZ + z)*C;
        ostride = (size_t)NY*NZ*C;
    } else if (BR == 1) {     // yz : n' = y ; fixed (x,z)
        int z = blockIdx.x, xx = blockIdx.y*2 + r;
        rrow = ((size_t)(b*NX + xx))*NZ + z;
        obase = (((size_t)(b*NX + xx)*NY)*NZ + z)*C;
        ostride = (size_t)NZ*C;
    } else {                  // xy : n' = x ; fixed (y,z)
        int y = blockIdx.x, z = blockIdx.y*2 + r;
        rrow = ((size_t)(b*NZ + z))*NY + y;
        obase = (((size_t)b*NX*NY + y)*NZ + z)*C;
        ostride = (size_t)NY*NZ*C;
    }
    switch (slot) {
        case 0: invAcc_body<0 >(rrow, obase, ostride, o); break;
        case 1: invAcc_body<8 >(rrow, obase, ostride, o); break;
        case 2: invAcc_body<16>(rrow, obase, ostride, o); break;
        case 3: invAcc_body<24>(rrow, obase, ostride, o); break;
        case 4: invAcc_body<32>(rrow, obase, ostride, o); break;
        case 5: invAcc_body<40>(rrow, obase, ostride, o); break;
        case 6: invAcc_body<48>(rrow, obase, ostride, o); break;
        default: invAcc_body<56>(rrow, obase, ostride, o); break;
    }
}

// ================= feedforward =================
__global__ void __launch_bounds__(256) k_ff(const float* __restrict__ w0,
                                            const float* __restrict__ b0,
                                            const float* __restrict__ w1,
                                            const float* __restrict__ b1,
                                            float* __restrict__ out) {
    __shared__ float w0t[C*64];
    __shared__ float w1t[64*C];
    __shared__ float b0s[64], b1s[C];
    __shared__ float as[8][C];
    __shared__ float h1s[8][64];
    int tid = threadIdx.x;
    for (int t = tid; t < C*64; t += 256) { int i = t / 64, h = t % 64; w0t[t] = w0[h*C + i]; }
    for (int t = tid; t < 64*C; t += 256) { int h = t / C,  o = t % C;  w1t[t] = w1[o*64 + h]; }
    if (tid < 64) b0s[tid] = b0[tid];
    if (tid < C)  b1s[tid] = b1[tid];
    __syncthreads();
    int lane = tid & 31, w = tid >> 5;
    const int TPW = 32;
    size_t t0 = ((size_t)blockIdx.x * 8 + w) * TPW;
    for (int j = 0; j < TPW; j++) {
        size_t t = t0 + j;
        as[w][lane] = g_acc[t*C + lane];
        __syncwarp();
        float h1a = b0s[lane], h1b = b0s[lane + 32];
        #pragma unroll
        for (int i = 0; i < C; i++) {
            float a = as[w][i];
            h1a += a * w0t[i*64 + lane];
            h1b += a * w0t[i*64 + lane + 32];
        }
        h1a = fmaxf(h1a, 0.f); h1b = fmaxf(h1b, 0.f);
        h1s[w][lane] = h1a; h1s[w][lane + 32] = h1b;
        __syncwarp();
        float v = b1s[lane];
        #pragma unroll
        for (int h = 0; h < 64; h++) v += h1s[w][h] * w1t[h*C + lane];
        out[t*C + lane] = v;
        __syncwarp();
    }
}

extern "C" void kernel_launch(void* const* d_in, const int* in_sizes, int n_in,
                              void* d_out, int out_size) {
    const float* x      = (const float*)d_in[0];
    const float* w      = (const float*)d_in[1];
    const float* wb     = (const float*)d_in[2];
    const float* fw_xy  = (const float*)d_in[3];
    const float* fw_yz  = (const float*)d_in[4];
    const float* fw_xz  = (const float*)d_in[5];
    const float* fw2_xy = (const float*)d_in[6];
    const float* fw2_yz = (const float*)d_in[7];
    const float* fw2_xz = (const float*)d_in[8];
    const float* ffw0   = (const float*)d_in[9];
    const float* ffb0   = (const float*)d_in[10];
    const float* ffw1   = (const float*)d_in[11];
    const float* ffb1   = (const float*)d_in[12];
    float* out = (float*)d_out;

    k_conv<<<dim3(NY, NX, NB), 640>>>(x, w, wb);

    // shared forward x-DFT (feeds xz + xy)
    k_fftx<0><<<dim3(5, NY, NB), 256>>>(x);
    k_fftx<8><<<dim3(5, NY, NB), 256>>>(x);

    // ---- xz branch ----
    k_zfftQ<0><<<dim3(8, KM, NB), 256>>>();
    k_zfftQ<8><<<dim3(8, KM, NB), 256>>>();
    k_mix<<<256, 1024>>>(fw_xz, fw2_xz, NB*NY, 8);
    k_invZ<<<dim3(32, KM, NB), 320>>>();
    k_invAcc<0><<<dim3(NZ, NY/2, NB), 512>>>();

    // ---- xy branch ----
    k_yfftQ<0 ><<<dim3(5, KM, NB), 256>>>();
    k_yfftQ<8 ><<<dim3(5, KM, NB), 256>>>();
    k_yfftQ<16><<<dim3(5, KM, NB), 256>>>();
    k_yfftQ<24><<<dim3(5, KM, NB), 256>>>();
    k_mix<<<512, 1024>>>(fw_xy, fw2_xy, NB*NZ, 16);
    k_invY<<<dim3(20, KM, NB), 512>>>();
    k_invAcc<2><<<dim3(NY, NZ/2, NB), 512>>>();

    // ---- yz branch ----
    k_rfftz<<<dim3(8, NX, NB), 256>>>(x);
    k_yfftP<0><<<dim3(2, NX, NB), 256>>>();
    k_yfftP<8><<<dim3(2, NX, NB), 256>>>();
    k_mix<<<256, 1024>>>(fw_yz, fw2_yz, NB*NX, 8);
    k_invZ<<<dim3(32, KM, NB), 320>>>();
    k_invAcc<1><<<dim3(NZ, NX/2, NB), 512>>>();

    // ---- feedforward ----
    k_ff<<<2560, 256>>>(ffw0, ffb0, ffw1, ffb1, out);
}